// round 3
// baseline (speedup 1.0000x reference)
#include <cuda_runtime.h>
#include <cuda_bf16.h>
#include <math.h>
#include <cstdint>

// Shapes (fixed)
#define Ln 4
#define Dn 512
#define Hn 2048
#define Vn 32000
#define Bn 2
#define Tn 2048
#define NTOK (Bn*Tn)   // 4096

// ---------------- scratch ----------------
__device__ float g_X [NTOK * Dn];
__device__ float g_Y [NTOK * Dn];
__device__ float g_XG[NTOK * Dn];
__device__ float g_Dv[NTOK];
__device__ float g_S [(long long)Bn * Tn * Tn];
__device__ float g_U [(long long)NTOK * Hn];

// ---------------- tf32 helpers ----------------
__device__ __forceinline__ uint32_t tf32_bits(float x) {
    uint32_t u;
    asm("cvt.rna.tf32.f32 %0, %1;" : "=r"(u) : "f"(x));
    return u;
}
__device__ __forceinline__ void mma_tf32(float* c, const uint32_t* a, const uint32_t* b) {
    asm volatile(
        "mma.sync.aligned.m16n8k8.row.col.f32.tf32.tf32.f32 "
        "{%0,%1,%2,%3}, {%4,%5,%6,%7}, {%8,%9}, {%0,%1,%2,%3};"
        : "+f"(c[0]), "+f"(c[1]), "+f"(c[2]), "+f"(c[3])
        : "r"(a[0]), "r"(a[1]), "r"(a[2]), "r"(a[3]), "r"(b[0]), "r"(b[1]));
}

// smem geometry
#define PADK 36                       // 36-float row pitch: frag bank = (4r+k)%32, conflict-free
#define STG_FLOATS (128 * PADK)       // one 128x32 tile (padded) = 4608 floats
#define STAGE_FLOATS (4 * STG_FLOATS) // Ahi | Alo | Bhi | Blo
#define SMEM_BYTES (2 * STAGE_FLOATS * 4)   // 147456 B
#define OPAD 132                      // epilogue bounce pitch

// ---------------- tf32x3 warp-MMA GEMM ----------------
// C[M,N] = A[M,K] @ op(B).  BNMAJ: B stored [K,N] (N-contig).  !BNMAJ: B stored [N,K] (K-contig).
// EPI: 0 store, 1 +bias, 2 gelu(+bias), 3 C+=acc, 4 C+=acc+bias
template<bool BNMAJ, int EPI>
__global__ __launch_bounds__(256)
void gemm_mma(const float* __restrict__ A, const float* __restrict__ B,
              float* __restrict__ C, const float* __restrict__ bias,
              int lda, int ldb, int ldc, int K,
              long long sA, long long sB, long long sC)
{
    extern __shared__ float sm[];
    const int tid = threadIdx.x;
    const int wid = tid >> 5, lane = tid & 31;
    const int qr = lane >> 2, qc = lane & 3;
    const int wm = (wid & 3) * 32;       // warp M offset in CTA tile
    const int wn = (wid >> 2) * 64;      // warp N offset
    const int m0 = blockIdx.x * 128, n0 = blockIdx.y * 128;
    A += (long long)blockIdx.z * sA + (long long)m0 * lda;
    B += (long long)blockIdx.z * sB;
    C += (long long)blockIdx.z * sC;

    float acc[2][8][4];
#pragma unroll
    for (int mt = 0; mt < 2; mt++)
#pragma unroll
        for (int nt = 0; nt < 8; nt++)
#pragma unroll
            for (int j = 0; j < 4; j++) acc[mt][nt][j] = 0.f;

    const int NC = K >> 5;

    // loader index decomposition (per thread, 4 iterations of 256 threads)
    // A (and !BNMAJ B): idx -> r = idx>>3 (row 0..127), q = idx&7 (float4 at k q*4)
    // BNMAJ B:          idx -> kk = idx>>5 (k 0..31),  nq = idx&31 (float4 at n nq*4)

    // ---- load + convert + store one chunk directly (used for chunk 0) ----
    auto load_chunk_direct = [&](int kc, float* stg) {
        float* Ah = stg;
        float* Al = stg + STG_FLOATS;
        float* Bh = stg + 2 * STG_FLOATS;
        float* Bl = stg + 3 * STG_FLOATS;
        const int k0 = kc << 5;
#pragma unroll
        for (int i = 0; i < 4; i++) {
            int idx = tid + i * 256;
            int r = idx >> 3, q = idx & 7;
            float4 v = *reinterpret_cast<const float4*>(&A[(long long)r * lda + k0 + q * 4]);
            float4 h, l;
            h.x = __uint_as_float(tf32_bits(v.x)); l.x = __uint_as_float(tf32_bits(v.x - h.x));
            h.y = __uint_as_float(tf32_bits(v.y)); l.y = __uint_as_float(tf32_bits(v.y - h.y));
            h.z = __uint_as_float(tf32_bits(v.z)); l.z = __uint_as_float(tf32_bits(v.z - h.z));
            h.w = __uint_as_float(tf32_bits(v.w)); l.w = __uint_as_float(tf32_bits(v.w - h.w));
            *reinterpret_cast<float4*>(&Ah[r * PADK + q * 4]) = h;
            *reinterpret_cast<float4*>(&Al[r * PADK + q * 4]) = l;
        }
        if (!BNMAJ) {
#pragma unroll
            for (int i = 0; i < 4; i++) {
                int idx = tid + i * 256;
                int r = idx >> 3, q = idx & 7;
                float4 v = *reinterpret_cast<const float4*>(&B[(long long)(n0 + r) * ldb + k0 + q * 4]);
                float4 h, l;
                h.x = __uint_as_float(tf32_bits(v.x)); l.x = __uint_as_float(tf32_bits(v.x - h.x));
                h.y = __uint_as_float(tf32_bits(v.y)); l.y = __uint_as_float(tf32_bits(v.y - h.y));
                h.z = __uint_as_float(tf32_bits(v.z)); l.z = __uint_as_float(tf32_bits(v.z - h.z));
                h.w = __uint_as_float(tf32_bits(v.w)); l.w = __uint_as_float(tf32_bits(v.w - h.w));
                *reinterpret_cast<float4*>(&Bh[r * PADK + q * 4]) = h;
                *reinterpret_cast<float4*>(&Bl[r * PADK + q * 4]) = l;
            }
        } else {
#pragma unroll
            for (int i = 0; i < 4; i++) {
                int idx = tid + i * 256;
                int kk = idx >> 5, nq = idx & 31;
                float4 v = *reinterpret_cast<const float4*>(&B[(long long)(k0 + kk) * ldb + n0 + nq * 4]);
                float vv[4] = {v.x, v.y, v.z, v.w};
#pragma unroll
                for (int c4 = 0; c4 < 4; c4++) {
                    int n = nq * 4 + c4;
                    float h = __uint_as_float(tf32_bits(vv[c4]));
                    Bh[n * PADK + kk] = h;
                    Bl[n * PADK + kk] = __uint_as_float(tf32_bits(vv[c4] - h));
                }
            }
        }
    };

    load_chunk_direct(0, sm);
    __syncthreads();

    for (int c = 0; c < NC; c++) {
        float* cur = sm + (c & 1) * STAGE_FLOATS;
        const bool pref = (c + 1 < NC);
        float4 pa[4], pb[4];
        if (pref) {
            const int k0 = (c + 1) << 5;
#pragma unroll
            for (int i = 0; i < 4; i++) {
                int idx = tid + i * 256;
                int r = idx >> 3, q = idx & 7;
                pa[i] = *reinterpret_cast<const float4*>(&A[(long long)r * lda + k0 + q * 4]);
                if (!BNMAJ) {
                    pb[i] = *reinterpret_cast<const float4*>(&B[(long long)(n0 + r) * ldb + k0 + q * 4]);
                } else {
                    int kk = idx >> 5, nq = idx & 31;
                    pb[i] = *reinterpret_cast<const float4*>(&B[(long long)(k0 + kk) * ldb + n0 + nq * 4]);
                }
            }
        }

        // ---- compute current chunk ----
        const float* Ah = cur;
        const float* Al = cur + STG_FLOATS;
        const float* Bh = cur + 2 * STG_FLOATS;
        const float* Bl = cur + 3 * STG_FLOATS;
#pragma unroll
        for (int ks = 0; ks < 4; ks++) {
            const int k0 = ks * 8;
            uint32_t ah[2][4], al[2][4];
#pragma unroll
            for (int mt = 0; mt < 2; mt++) {
                int r = wm + mt * 16 + qr;
                const float* p = Ah + r * PADK + k0 + qc;
                ah[mt][0] = __float_as_uint(p[0]);
                ah[mt][1] = __float_as_uint(p[8 * PADK]);
                ah[mt][2] = __float_as_uint(p[4]);
                ah[mt][3] = __float_as_uint(p[8 * PADK + 4]);
                const float* pl = Al + r * PADK + k0 + qc;
                al[mt][0] = __float_as_uint(pl[0]);
                al[mt][1] = __float_as_uint(pl[8 * PADK]);
                al[mt][2] = __float_as_uint(pl[4]);
                al[mt][3] = __float_as_uint(pl[8 * PADK + 4]);
            }
#pragma unroll
            for (int nt = 0; nt < 8; nt++) {
                int n = wn + nt * 8 + qr;
                const float* q0 = Bh + n * PADK + k0 + qc;
                uint32_t bh[2] = {__float_as_uint(q0[0]), __float_as_uint(q0[4])};
                const float* q1 = Bl + n * PADK + k0 + qc;
                uint32_t bl[2] = {__float_as_uint(q1[0]), __float_as_uint(q1[4])};
#pragma unroll
                for (int mt = 0; mt < 2; mt++) {
                    mma_tf32(acc[mt][nt], ah[mt], bh);
                    mma_tf32(acc[mt][nt], ah[mt], bl);
                    mma_tf32(acc[mt][nt], al[mt], bh);
                }
            }
        }

        // ---- convert + store prefetched chunk into the other buffer ----
        if (pref) {
            float* nx = sm + ((c + 1) & 1) * STAGE_FLOATS;
            float* Ahn = nx;
            float* Aln = nx + STG_FLOATS;
            float* Bhn = nx + 2 * STG_FLOATS;
            float* Bln = nx + 3 * STG_FLOATS;
#pragma unroll
            for (int i = 0; i < 4; i++) {
                int idx = tid + i * 256;
                int r = idx >> 3, q = idx & 7;
                float4 v = pa[i];
                float4 h, l;
                h.x = __uint_as_float(tf32_bits(v.x)); l.x = __uint_as_float(tf32_bits(v.x - h.x));
                h.y = __uint_as_float(tf32_bits(v.y)); l.y = __uint_as_float(tf32_bits(v.y - h.y));
                h.z = __uint_as_float(tf32_bits(v.z)); l.z = __uint_as_float(tf32_bits(v.z - h.z));
                h.w = __uint_as_float(tf32_bits(v.w)); l.w = __uint_as_float(tf32_bits(v.w - h.w));
                *reinterpret_cast<float4*>(&Ahn[r * PADK + q * 4]) = h;
                *reinterpret_cast<float4*>(&Aln[r * PADK + q * 4]) = l;
                if (!BNMAJ) {
                    float4 w = pb[i];
                    float4 h2, l2;
                    h2.x = __uint_as_float(tf32_bits(w.x)); l2.x = __uint_as_float(tf32_bits(w.x - h2.x));
                    h2.y = __uint_as_float(tf32_bits(w.y)); l2.y = __uint_as_float(tf32_bits(w.y - h2.y));
                    h2.z = __uint_as_float(tf32_bits(w.z)); l2.z = __uint_as_float(tf32_bits(w.z - h2.z));
                    h2.w = __uint_as_float(tf32_bits(w.w)); l2.w = __uint_as_float(tf32_bits(w.w - h2.w));
                    *reinterpret_cast<float4*>(&Bhn[r * PADK + q * 4]) = h2;
                    *reinterpret_cast<float4*>(&Bln[r * PADK + q * 4]) = l2;
                } else {
                    int kk = idx >> 5, nq = idx & 31;
                    float4 w = pb[i];
                    float vv[4] = {w.x, w.y, w.z, w.w};
#pragma unroll
                    for (int c4 = 0; c4 < 4; c4++) {
                        int n = nq * 4 + c4;
                        float h2 = __uint_as_float(tf32_bits(vv[c4]));
                        Bhn[n * PADK + kk] = h2;
                        Bln[n * PADK + kk] = __uint_as_float(tf32_bits(vv[c4] - h2));
                    }
                }
            }
        }
        __syncthreads();
    }

    // ---- epilogue: bounce through smem for coalesced stores ----
    float* Cs = sm;
#pragma unroll
    for (int mt = 0; mt < 2; mt++)
#pragma unroll
        for (int nt = 0; nt < 8; nt++) {
            int r = wm + mt * 16 + qr;
            int col = wn + nt * 8 + qc * 2;
            *reinterpret_cast<float2*>(&Cs[r * OPAD + col]) =
                make_float2(acc[mt][nt][0], acc[mt][nt][1]);
            *reinterpret_cast<float2*>(&Cs[(r + 8) * OPAD + col]) =
                make_float2(acc[mt][nt][2], acc[mt][nt][3]);
        }
    __syncthreads();

    {
        int row = tid >> 1, hf = tid & 1;
        long long gr = m0 + row;
#pragma unroll
        for (int j = 0; j < 16; j++) {
            int cl = hf * 64 + j * 4;
            float4 v = *reinterpret_cast<float4*>(&Cs[row * OPAD + cl]);
            int coln = n0 + cl;
            float* cp = &C[gr * (long long)ldc + coln];
            float vv[4] = {v.x, v.y, v.z, v.w};
            if (EPI == 1 || EPI == 2 || EPI == 4) {
                float4 bb = *reinterpret_cast<const float4*>(&bias[coln]);
                vv[0] += bb.x; vv[1] += bb.y; vv[2] += bb.z; vv[3] += bb.w;
            }
            if (EPI == 2) {
#pragma unroll
                for (int e = 0; e < 4; e++)
                    vv[e] = 0.5f * vv[e] * (1.0f + erff(vv[e] * 0.70710678118654752f));
            }
            if (EPI == 3 || EPI == 4) {
                float4 o = *reinterpret_cast<const float4*>(cp);
                vv[0] += o.x; vv[1] += o.y; vv[2] += o.z; vv[3] += o.w;
            }
            float4 s = make_float4(vv[0], vv[1], vv[2], vv[3]);
            *reinterpret_cast<float4*>(cp) = s;
        }
    }
}

// ---------------- elementwise kernels ----------------
__global__ void embed_kernel(const int* __restrict__ ids, const float* __restrict__ emb,
                             float* __restrict__ X)
{
    long long i = (long long)blockIdx.x * 256 + threadIdx.x;
    int tok = (int)(i >> 9);
    int d   = (int)(i & 511);
    X[i] = emb[(long long)ids[tok] * Dn + d];
}

__global__ void layernorm_kernel(const float* __restrict__ in, float* __restrict__ out,
                                 const float* __restrict__ gamma, const float* __restrict__ beta)
{
    int tok = blockIdx.x;
    const float* x = in + (long long)tok * Dn;
    int t = threadIdx.x;
    float v0 = x[t], v1 = x[t + 256];
    float s = v0 + v1, s2 = v0 * v0 + v1 * v1;
#pragma unroll
    for (int o = 16; o; o >>= 1) {
        s  += __shfl_xor_sync(0xffffffffu, s,  o);
        s2 += __shfl_xor_sync(0xffffffffu, s2, o);
    }
    __shared__ float ss[8], ss2[8];
    int w = t >> 5, lane = t & 31;
    if (lane == 0) { ss[w] = s; ss2[w] = s2; }
    __syncthreads();
    if (w == 0) {
        s  = (lane < 8) ? ss[lane]  : 0.f;
        s2 = (lane < 8) ? ss2[lane] : 0.f;
#pragma unroll
        for (int o = 4; o; o >>= 1) {
            s  += __shfl_xor_sync(0xffffffffu, s,  o);
            s2 += __shfl_xor_sync(0xffffffffu, s2, o);
        }
        if (lane == 0) { ss[0] = s; ss2[0] = s2; }
    }
    __syncthreads();
    float mu  = ss[0] * (1.f / Dn);
    float var = ss2[0] * (1.f / Dn) - mu * mu;
    float inv = rsqrtf(var + 1e-5f);
    float* o = out + (long long)tok * Dn;
    o[t]       = (v0 - mu) * inv * gamma[t]       + beta[t];
    o[t + 256] = (v1 - mu) * inv * gamma[t + 256] + beta[t + 256];
}

__global__ void diag_kernel(const float* __restrict__ S, float* __restrict__ d)
{
    int i = blockIdx.x * 256 + threadIdx.x;
    int b = i / Tn, t = i % Tn;
    d[i] = S[(long long)b * Tn * Tn + (long long)t * (Tn + 1)];
}

__global__ void softmax_kernel(float* __restrict__ S, const float* __restrict__ d)
{
    int b = blockIdx.y, t = blockIdx.x;
    float* row = S + (long long)b * Tn * Tn + (long long)t * Tn;
    const float* db = d + b * Tn;
    int tid = threadIdx.x;
    float v[8];
    float mx = -1e30f;
#pragma unroll
    for (int r = 0; r < 8; r++) {
        int j = tid + r * 256;
        v[r] = 2.f * row[j] - db[j];
        mx = fmaxf(mx, v[r]);
    }
    __shared__ float red[8];
#pragma unroll
    for (int o = 16; o; o >>= 1) mx = fmaxf(mx, __shfl_xor_sync(0xffffffffu, mx, o));
    int w = tid >> 5, lane = tid & 31;
    if (lane == 0) red[w] = mx;
    __syncthreads();
    if (w == 0) {
        mx = (lane < 8) ? red[lane] : -1e30f;
#pragma unroll
        for (int o = 4; o; o >>= 1) mx = fmaxf(mx, __shfl_xor_sync(0xffffffffu, mx, o));
        if (lane == 0) red[0] = mx;
    }
    __syncthreads();
    mx = red[0];
    float sum = 0.f;
#pragma unroll
    for (int r = 0; r < 8; r++) { v[r] = expf(v[r] - mx); sum += v[r]; }
    __syncthreads();
#pragma unroll
    for (int o = 16; o; o >>= 1) sum += __shfl_xor_sync(0xffffffffu, sum, o);
    if (lane == 0) red[w] = sum;
    __syncthreads();
    if (w == 0) {
        sum = (lane < 8) ? red[lane] : 0.f;
#pragma unroll
        for (int o = 4; o; o >>= 1) sum += __shfl_xor_sync(0xffffffffu, sum, o);
        if (lane == 0) red[0] = sum;
    }
    __syncthreads();
    float inv = 1.f / red[0];
#pragma unroll
    for (int r = 0; r < 8; r++) row[tid + r * 256] = v[r] * inv;
}

// ---------------- launch ----------------
extern "C" void kernel_launch(void* const* d_in, const int* in_sizes, int n_in,
                              void* d_out, int out_size)
{
    const int*   ids   = (const int*)  d_in[0];
    const float* emb   = (const float*)d_in[1];
    const float* g     = (const float*)d_in[2];
    const float* W1    = (const float*)d_in[3];
    const float* b1    = (const float*)d_in[4];
    const float* W2    = (const float*)d_in[5];
    const float* b2    = (const float*)d_in[6];
    const float* ln1s  = (const float*)d_in[7];
    const float* ln1b  = (const float*)d_in[8];
    const float* ln2s  = (const float*)d_in[9];
    const float* ln2b  = (const float*)d_in[10];
    const float* lnfs  = (const float*)d_in[11];
    const float* lnfb  = (const float*)d_in[12];
    const float* headw = (const float*)d_in[13];
    const float* headb = (const float*)d_in[14];
    float* out = (float*)d_out;

    float *pX, *pY, *pXG, *pD, *pS, *pU;
    cudaGetSymbolAddress((void**)&pX,  g_X);
    cudaGetSymbolAddress((void**)&pY,  g_Y);
    cudaGetSymbolAddress((void**)&pXG, g_XG);
    cudaGetSymbolAddress((void**)&pD,  g_Dv);
    cudaGetSymbolAddress((void**)&pS,  g_S);
    cudaGetSymbolAddress((void**)&pU,  g_U);

    static bool attr_done = false;
    if (!attr_done) {
        cudaFuncSetAttribute(gemm_mma<true, 0>,  cudaFuncAttributeMaxDynamicSharedMemorySize, SMEM_BYTES);
        cudaFuncSetAttribute(gemm_mma<false, 0>, cudaFuncAttributeMaxDynamicSharedMemorySize, SMEM_BYTES);
        cudaFuncSetAttribute(gemm_mma<true, 1>,  cudaFuncAttributeMaxDynamicSharedMemorySize, SMEM_BYTES);
        cudaFuncSetAttribute(gemm_mma<true, 2>,  cudaFuncAttributeMaxDynamicSharedMemorySize, SMEM_BYTES);
        cudaFuncSetAttribute(gemm_mma<true, 3>,  cudaFuncAttributeMaxDynamicSharedMemorySize, SMEM_BYTES);
        cudaFuncSetAttribute(gemm_mma<true, 4>,  cudaFuncAttributeMaxDynamicSharedMemorySize, SMEM_BYTES);
        attr_done = true;
    }

    embed_kernel<<<(NTOK * Dn) / 256, 256>>>(ids, emb, pX);

    for (int l = 0; l < Ln; l++) {
        layernorm_kernel<<<NTOK, 256>>>(pX, pY, ln1s + l * Dn, ln1b + l * Dn);
        // xg = y @ G[l]   (G symmetric; stored [K=D, N=D] N-contig)
        gemm_mma<true, 0><<<dim3(NTOK / 128, Dn / 128, 1), 256, SMEM_BYTES>>>(
            pY, g + (long long)l * Dn * Dn, pXG, nullptr,
            Dn, Dn, Dn, Dn, 0, 0, 0);
        // S_b = XG_b @ Y_b^T   (B = Y stored [N=T, K=D] K-contig)
        gemm_mma<false, 0><<<dim3(Tn / 128, Tn / 128, Bn), 256, SMEM_BYTES>>>(
            pXG, pY, pS, nullptr,
            Dn, Dn, Tn, Dn, (long long)Tn * Dn, (long long)Tn * Dn, (long long)Tn * Tn);
        diag_kernel<<<NTOK / 256, 256>>>(pS, pD);
        softmax_kernel<<<dim3(Tn, Bn), 256>>>(pS, pD);
        // x += P_b @ Y_b   (B = Y stored [K=T, N=D] N-contig)
        gemm_mma<true, 3><<<dim3(Tn / 128, Dn / 128, Bn), 256, SMEM_BYTES>>>(
            pS, pY, pX, nullptr,
            Tn, Dn, Dn, Tn, (long long)Tn * Tn, (long long)Tn * Dn, (long long)Tn * Dn);
        layernorm_kernel<<<NTOK, 256>>>(pX, pY, ln2s + l * Dn, ln2b + l * Dn);
        // u = gelu(h @ W1 + b1)   (W1 stored [K=D, N=H] N-contig)
        gemm_mma<true, 2><<<dim3(NTOK / 128, Hn / 128, 1), 256, SMEM_BYTES>>>(
            pY, W1 + (long long)l * Dn * Hn, pU, b1 + l * Hn,
            Dn, Hn, Hn, Dn, 0, 0, 0);
        // x += u @ W2 + b2   (W2 stored [K=H, N=D] N-contig)
        gemm_mma<true, 4><<<dim3(NTOK / 128, Dn / 128, 1), 256, SMEM_BYTES>>>(
            pU, W2 + (long long)l * Hn * Dn, pX, b2 + l * Dn,
            Hn, Dn, Dn, Hn, 0, 0, 0);
    }
    layernorm_kernel<<<NTOK, 256>>>(pX, pY, lnfs, lnfb);
    // out = y @ head_w + head_b   (head_w stored [K=D, N=V] N-contig)
    gemm_mma<true, 1><<<dim3(NTOK / 128, Vn / 128, 1), 256, SMEM_BYTES>>>(
        pY, headw, out, headb,
        Dn, Vn, Vn, Dn, 0, 0, 0);
}

// round 9
// speedup vs baseline: 2.6646x; 2.6646x over previous
#include <cuda_runtime.h>
#include <cuda_bf16.h>
#include <math.h>
#include <cstdint>

// Shapes (fixed)
#define Ln 4
#define Dn 512
#define Hn 2048
#define Vn 32000
#define Bn 2
#define Tn 2048
#define NTOK (Bn*Tn)   // 4096

typedef __nv_bfloat16 bf16;

// ---------------- scratch ----------------
__device__ float g_X [NTOK * Dn];                 // fp32 residual
__device__ float g_S [(long long)Bn * Tn * Tn];   // fp32 scores
__device__ float g_Dv[NTOK];
__device__ bf16  g_Yh[NTOK * Dn],  g_Yl[NTOK * Dn];
__device__ bf16  g_Yth[NTOK * Dn], g_Ytl[NTOK * Dn];   // Y^T per batch [B][D][T]
__device__ bf16  g_XGh[NTOK * Dn];
__device__ bf16  g_Ph[(long long)Bn * Tn * Tn], g_Pl[(long long)Bn * Tn * Tn];
__device__ bf16  g_Uh[(long long)NTOK * Hn], g_Ul[(long long)NTOK * Hn];
__device__ bf16  g_Gh [Ln * Dn * Dn];
__device__ bf16  g_W1h[Ln * Hn * Dn], g_W1l[Ln * Hn * Dn];   // transposed [H,D]
__device__ bf16  g_W2h[Ln * Dn * Hn], g_W2l[Ln * Dn * Hn];   // transposed [D,H]
__device__ bf16  g_HWh[(long long)Vn * Dn], g_HWl[(long long)Vn * Dn]; // transposed [V,D]

// ---------------- helpers ----------------
__device__ __forceinline__ uint32_t smem_u32(const void* p) {
    uint32_t a;
    asm("{ .reg .u64 t; cvta.to.shared.u64 t, %1; cvt.u32.u64 %0, t; }" : "=r"(a) : "l"(p));
    return a;
}
__device__ __forceinline__ void cp16(uint32_t dst, const void* src) {
    asm volatile("cp.async.cg.shared.global [%0], [%1], 16;" :: "r"(dst), "l"(src));
}
__device__ __forceinline__ void cp_commit() {
    asm volatile("cp.async.commit_group;" ::: "memory");
}
template<int N>
__device__ __forceinline__ void cp_wait() {
    asm volatile("cp.async.wait_group %0;" :: "n"(N) : "memory");
}
__device__ __forceinline__ void mma_bf16(float* c, const uint32_t* a, const uint32_t* b) {
    asm volatile(
        "mma.sync.aligned.m16n8k16.row.col.f32.bf16.bf16.f32 "
        "{%0,%1,%2,%3}, {%4,%5,%6,%7}, {%8,%9}, {%0,%1,%2,%3};"
        : "+f"(c[0]), "+f"(c[1]), "+f"(c[2]), "+f"(c[3])
        : "r"(a[0]), "r"(a[1]), "r"(a[2]), "r"(a[3]), "r"(b[0]), "r"(b[1]));
}
__device__ __forceinline__ void split2(float x, bf16& h, bf16& l) {
    h = __float2bfloat16_rn(x);
    l = __float2bfloat16_rn(x - __bfloat162float(h));
}

// smem geometry: bf16 tile 128 rows x 32 k, row pitch 80B
#define TILEB 10240
#define OPAD 132

// ---------------- bf16 split GEMM ----------------
// C[M,N] = A[M,K] @ B^T, with B stored [N,K] (K-contig rows), hi(/lo) bf16 pairs.
// NT: 1 (hi*hi) or 3 (hh + hl + lh)
// EPI: 0 C=acc; 1 C=acc+bias; 2 Oh/Ol=split(gelu(acc+bias)); 3 C+=acc; 4 C+=acc+bias; 5 Oh=bf16(acc)
template<int NT, int EPI>
__global__ __launch_bounds__(256, 2)
void gemm_bf16(const bf16* __restrict__ Agh, const bf16* __restrict__ Agl,
               const bf16* __restrict__ Bgh, const bf16* __restrict__ Bgl,
               float* __restrict__ C, bf16* __restrict__ Oh, bf16* __restrict__ Ol,
               const float* __restrict__ bias, int K, int ldc,
               long long sA, long long sB, long long sC)
{
    extern __shared__ char sm[];
    const int tid = threadIdx.x, wid = tid >> 5, lane = tid & 31;
    const int qr = lane >> 2, qc = lane & 3;
    const int wm = (wid & 3) * 32, wn = (wid >> 2) * 64;
    const int m0 = blockIdx.x * 128, n0 = blockIdx.y * 128;
    Agh += (long long)blockIdx.z * sA + (long long)m0 * K;
    Bgh += (long long)blockIdx.z * sB + (long long)n0 * K;
    if (NT == 3) {
        Agl += (long long)blockIdx.z * sA + (long long)m0 * K;
        Bgl += (long long)blockIdx.z * sB + (long long)n0 * K;
    }
    // FIX (round 8): batch offset for ALL output pointers
    if (C)  C  += (long long)blockIdx.z * sC;
    if (Oh) Oh += (long long)blockIdx.z * sC;
    if (Ol) Ol += (long long)blockIdx.z * sC;

    const uint32_t sbase = smem_u32(sm);
    constexpr int STAGE = (NT == 3 ? 4 : 2) * TILEB;
    constexpr int AHI = 0, BHI = TILEB, ALO = 2 * TILEB, BLO = 3 * TILEB;

    float acc[2][8][4];
#pragma unroll
    for (int mt = 0; mt < 2; mt++)
#pragma unroll
        for (int nt = 0; nt < 8; nt++)
#pragma unroll
            for (int j = 0; j < 4; j++) acc[mt][nt][j] = 0.f;

    const int NC = K >> 5;
    const int lr = tid >> 2, lq = tid & 3;
    const int lr2 = (tid + 256) >> 2, lq2 = (tid + 256) & 3;

    auto issue = [&](int c) {
        const int k0 = c << 5;
        const uint32_t st = sbase + (c & 1) * STAGE;
        {
            uint32_t doff = lr * 80 + lq * 16;
            cp16(st + AHI + doff, (const char*)(Agh + (long long)lr * K + k0) + lq * 16);
            cp16(st + BHI + doff, (const char*)(Bgh + (long long)lr * K + k0) + lq * 16);
            if (NT == 3) {
                cp16(st + ALO + doff, (const char*)(Agl + (long long)lr * K + k0) + lq * 16);
                cp16(st + BLO + doff, (const char*)(Bgl + (long long)lr * K + k0) + lq * 16);
            }
        }
        {
            uint32_t doff = lr2 * 80 + lq2 * 16;
            cp16(st + AHI + doff, (const char*)(Agh + (long long)lr2 * K + k0) + lq2 * 16);
            cp16(st + BHI + doff, (const char*)(Bgh + (long long)lr2 * K + k0) + lq2 * 16);
            if (NT == 3) {
                cp16(st + ALO + doff, (const char*)(Agl + (long long)lr2 * K + k0) + lq2 * 16);
                cp16(st + BLO + doff, (const char*)(Bgl + (long long)lr2 * K + k0) + lq2 * 16);
            }
        }
    };

    issue(0); cp_commit();
    issue(1); cp_commit();

    for (int c = 0; c < NC; c++) {
        cp_wait<1>();
        __syncthreads();
        const char* st = sm + (c & 1) * STAGE;
#pragma unroll
        for (int ks = 0; ks < 2; ks++) {
            const int kb = ks * 32 + qc * 4;
            uint32_t a0[2][4], a1[2][4];
#pragma unroll
            for (int mt = 0; mt < 2; mt++) {
                const int rb = (wm + mt * 16 + qr) * 80 + kb;
                a0[mt][0] = *(const uint32_t*)(st + AHI + rb);
                a0[mt][1] = *(const uint32_t*)(st + AHI + rb + 640);
                a0[mt][2] = *(const uint32_t*)(st + AHI + rb + 16);
                a0[mt][3] = *(const uint32_t*)(st + AHI + rb + 656);
                if (NT == 3) {
                    a1[mt][0] = *(const uint32_t*)(st + ALO + rb);
                    a1[mt][1] = *(const uint32_t*)(st + ALO + rb + 640);
                    a1[mt][2] = *(const uint32_t*)(st + ALO + rb + 16);
                    a1[mt][3] = *(const uint32_t*)(st + ALO + rb + 656);
                }
            }
#pragma unroll
            for (int nt = 0; nt < 8; nt++) {
                const int nb = (wn + nt * 8 + qr) * 80 + kb;
                uint32_t b0[2] = { *(const uint32_t*)(st + BHI + nb),
                                   *(const uint32_t*)(st + BHI + nb + 16) };
#pragma unroll
                for (int mt = 0; mt < 2; mt++) mma_bf16(acc[mt][nt], a0[mt], b0);
                if (NT == 3) {
                    uint32_t b1[2] = { *(const uint32_t*)(st + BLO + nb),
                                       *(const uint32_t*)(st + BLO + nb + 16) };
#pragma unroll
                    for (int mt = 0; mt < 2; mt++) {
                        mma_bf16(acc[mt][nt], a0[mt], b1);
                        mma_bf16(acc[mt][nt], a1[mt], b0);
                    }
                }
            }
        }
        __syncthreads();
        if (c + 2 < NC) issue(c + 2);
        cp_commit();
    }

    // ---- epilogue: bounce through smem for coalesced rows ----
    float* Cs = reinterpret_cast<float*>(sm);
#pragma unroll
    for (int mt = 0; mt < 2; mt++)
#pragma unroll
        for (int nt = 0; nt < 8; nt++) {
            int r = wm + mt * 16 + qr;
            int col = wn + nt * 8 + qc * 2;
            *reinterpret_cast<float2*>(&Cs[r * OPAD + col]) =
                make_float2(acc[mt][nt][0], acc[mt][nt][1]);
            *reinterpret_cast<float2*>(&Cs[(r + 8) * OPAD + col]) =
                make_float2(acc[mt][nt][2], acc[mt][nt][3]);
        }
    __syncthreads();

    {
        const int row = tid >> 1, hf = tid & 1;
        const long long gr = m0 + row;
#pragma unroll
        for (int j = 0; j < 16; j++) {
            const int cl = hf * 64 + j * 4;
            float4 v = *reinterpret_cast<float4*>(&Cs[row * OPAD + cl]);
            const int coln = n0 + cl;
            float vv[4] = {v.x, v.y, v.z, v.w};
            if (EPI == 1 || EPI == 2 || EPI == 4) {
                float4 bb = *reinterpret_cast<const float4*>(&bias[coln]);
                vv[0] += bb.x; vv[1] += bb.y; vv[2] += bb.z; vv[3] += bb.w;
            }
            if (EPI == 2) {
#pragma unroll
                for (int e = 0; e < 4; e++)
                    vv[e] = 0.5f * vv[e] * (1.0f + erff(vv[e] * 0.70710678118654752f));
            }
            if (EPI == 0 || EPI == 1 || EPI == 3 || EPI == 4) {
                float* cp = &C[gr * (long long)ldc + coln];
                if (EPI == 3 || EPI == 4) {
                    float4 o = *reinterpret_cast<const float4*>(cp);
                    vv[0] += o.x; vv[1] += o.y; vv[2] += o.z; vv[3] += o.w;
                }
                *reinterpret_cast<float4*>(cp) = make_float4(vv[0], vv[1], vv[2], vv[3]);
            } else {
                bf16* op = &Oh[gr * (long long)ldc + coln];
                if (EPI == 5) {
                    __nv_bfloat162 h01, h23;
                    h01.x = __float2bfloat16_rn(vv[0]); h01.y = __float2bfloat16_rn(vv[1]);
                    h23.x = __float2bfloat16_rn(vv[2]); h23.y = __float2bfloat16_rn(vv[3]);
                    *reinterpret_cast<__nv_bfloat162*>(op)     = h01;
                    *reinterpret_cast<__nv_bfloat162*>(op + 2) = h23;
                } else { // EPI 2
                    bf16 h[4], l[4];
#pragma unroll
                    for (int e = 0; e < 4; e++) split2(vv[e], h[e], l[e]);
                    __nv_bfloat162 h01, h23, l01, l23;
                    h01.x = h[0]; h01.y = h[1]; h23.x = h[2]; h23.y = h[3];
                    l01.x = l[0]; l01.y = l[1]; l23.x = l[2]; l23.y = l[3];
                    *reinterpret_cast<__nv_bfloat162*>(op)     = h01;
                    *reinterpret_cast<__nv_bfloat162*>(op + 2) = h23;
                    bf16* lp = &Ol[gr * (long long)ldc + coln];
                    *reinterpret_cast<__nv_bfloat162*>(lp)     = l01;
                    *reinterpret_cast<__nv_bfloat162*>(lp + 2) = l23;
                }
            }
        }
    }
}

// ---------------- prep kernels ----------------
__global__ void embed_kernel(const int* __restrict__ ids, const float* __restrict__ emb,
                             float* __restrict__ X)
{
    long long i = (long long)blockIdx.x * 256 + threadIdx.x;
    int tok = (int)(i >> 9);
    int d   = (int)(i & 511);
    X[i] = emb[(long long)ids[tok] * Dn + d];
}

// W [K,N] fp32 -> Wh,Wl [N,K] bf16 (batched over z)
__global__ void transpose_split(const float* __restrict__ in, bf16* __restrict__ oh,
                                bf16* __restrict__ ol, int K, int N)
{
    __shared__ float t[32][33];
    const int k0 = blockIdx.y * 32, n0 = blockIdx.x * 32;
    const long long base = (long long)blockIdx.z * K * N;
    const int tx = threadIdx.x, ty = threadIdx.y;
#pragma unroll
    for (int i = 0; i < 32; i += 8)
        t[ty + i][tx] = in[base + (long long)(k0 + ty + i) * N + n0 + tx];
    __syncthreads();
#pragma unroll
    for (int i = 0; i < 32; i += 8) {
        float x = t[tx][ty + i];
        bf16 h, l; split2(x, h, l);
        long long o = base + (long long)(n0 + ty + i) * K + k0 + tx;
        oh[o] = h; ol[o] = l;
    }
}

// bf16 pair transpose: [B][T,D] -> [B][D,T]
__global__ void transpose_pair(const bf16* __restrict__ ih, const bf16* __restrict__ il,
                               bf16* __restrict__ oh, bf16* __restrict__ ol)
{
    __shared__ bf16 th[32][33], tl[32][33];
    const int t0 = blockIdx.x * 32, d0 = blockIdx.y * 32;
    const int tx = threadIdx.x, ty = threadIdx.y;
    const long long ibase = (long long)blockIdx.z * Tn * Dn;
#pragma unroll
    for (int i = 0; i < 32; i += 8) {
        long long src = ibase + (long long)(t0 + ty + i) * Dn + d0 + tx;
        th[ty + i][tx] = ih[src];
        tl[ty + i][tx] = il[src];
    }
    __syncthreads();
#pragma unroll
    for (int i = 0; i < 32; i += 8) {
        long long dst = ibase + (long long)(d0 + ty + i) * Tn + t0 + tx;
        oh[dst] = th[tx][ty + i];
        ol[dst] = tl[tx][ty + i];
    }
}

__global__ void split_hi(const float* __restrict__ in, bf16* __restrict__ oh)
{
    long long i = (long long)blockIdx.x * 256 + threadIdx.x;
    oh[i] = __float2bfloat16_rn(in[i]);
}

// ---------------- layernorm -> bf16 pair ----------------
__global__ void layernorm_kernel(const float* __restrict__ in, bf16* __restrict__ oh,
                                 bf16* __restrict__ ol,
                                 const float* __restrict__ gamma, const float* __restrict__ beta)
{
    int tok = blockIdx.x;
    const float* x = in + (long long)tok * Dn;
    int t = threadIdx.x;
    float v0 = x[t], v1 = x[t + 256];
    float s = v0 + v1, s2 = v0 * v0 + v1 * v1;
#pragma unroll
    for (int o = 16; o; o >>= 1) {
        s  += __shfl_xor_sync(0xffffffffu, s,  o);
        s2 += __shfl_xor_sync(0xffffffffu, s2, o);
    }
    __shared__ float ss[8], ss2[8];
    int w = t >> 5, lane = t & 31;
    if (lane == 0) { ss[w] = s; ss2[w] = s2; }
    __syncthreads();
    if (w == 0) {
        s  = (lane < 8) ? ss[lane]  : 0.f;
        s2 = (lane < 8) ? ss2[lane] : 0.f;
#pragma unroll
        for (int o = 4; o; o >>= 1) {
            s  += __shfl_xor_sync(0xffffffffu, s,  o);
            s2 += __shfl_xor_sync(0xffffffffu, s2, o);
        }
        if (lane == 0) { ss[0] = s; ss2[0] = s2; }
    }
    __syncthreads();
    float mu  = ss[0] * (1.f / Dn);
    float var = ss2[0] * (1.f / Dn) - mu * mu;
    float inv = rsqrtf(var + 1e-5f);
    long long base = (long long)tok * Dn;
    float y0 = (v0 - mu) * inv * gamma[t]       + beta[t];
    float y1 = (v1 - mu) * inv * gamma[t + 256] + beta[t + 256];
    bf16 h, l;
    split2(y0, h, l); oh[base + t] = h;       ol[base + t] = l;
    split2(y1, h, l); oh[base + t + 256] = h; ol[base + t + 256] = l;
}

__global__ void diag_kernel(const float* __restrict__ S, float* __restrict__ d)
{
    int i = blockIdx.x * 256 + threadIdx.x;
    int b = i / Tn, t = i % Tn;
    d[i] = S[(long long)b * Tn * Tn + (long long)t * (Tn + 1)];
}

// softmax of (2S - d_j) -> bf16 pair
__global__ void softmax_kernel(const float* __restrict__ S, const float* __restrict__ d,
                               bf16* __restrict__ Ph, bf16* __restrict__ Pl)
{
    int b = blockIdx.y, t = blockIdx.x;
    const float* row = S + (long long)b * Tn * Tn + (long long)t * Tn;
    const float* db = d + b * Tn;
    int tid = threadIdx.x;
    float v[8];
    float mx = -1e30f;
#pragma unroll
    for (int r = 0; r < 8; r++) {
        int j = tid + r * 256;
        v[r] = 2.f * row[j] - db[j];
        mx = fmaxf(mx, v[r]);
    }
    __shared__ float red[8];
#pragma unroll
    for (int o = 16; o; o >>= 1) mx = fmaxf(mx, __shfl_xor_sync(0xffffffffu, mx, o));
    int w = tid >> 5, lane = tid & 31;
    if (lane == 0) red[w] = mx;
    __syncthreads();
    if (w == 0) {
        mx = (lane < 8) ? red[lane] : -1e30f;
#pragma unroll
        for (int o = 4; o; o >>= 1) mx = fmaxf(mx, __shfl_xor_sync(0xffffffffu, mx, o));
        if (lane == 0) red[0] = mx;
    }
    __syncthreads();
    mx = red[0];
    float sum = 0.f;
#pragma unroll
    for (int r = 0; r < 8; r++) { v[r] = expf(v[r] - mx); sum += v[r]; }
    __syncthreads();
#pragma unroll
    for (int o = 16; o; o >>= 1) sum += __shfl_xor_sync(0xffffffffu, sum, o);
    if (lane == 0) red[w] = sum;
    __syncthreads();
    if (w == 0) {
        sum = (lane < 8) ? red[lane] : 0.f;
#pragma unroll
        for (int o = 4; o; o >>= 1) sum += __shfl_xor_sync(0xffffffffu, sum, o);
        if (lane == 0) red[0] = sum;
    }
    __syncthreads();
    float inv = 1.f / red[0];
    long long base = (long long)b * Tn * Tn + (long long)t * Tn;
#pragma unroll
    for (int r = 0; r < 8; r++) {
        float p = v[r] * inv;
        bf16 h, l; split2(p, h, l);
        Ph[base + tid + r * 256] = h;
        Pl[base + tid + r * 256] = l;
    }
}

// ---------------- launch ----------------
#define SMEM3 (4 * TILEB * 2)                       // 81920
#define SMEM1 (128 * OPAD * 4)                      // 67584 (> 2*2*TILEB)

extern "C" void kernel_launch(void* const* d_in, const int* in_sizes, int n_in,
                              void* d_out, int out_size)
{
    const int*   ids   = (const int*)  d_in[0];
    const float* emb   = (const float*)d_in[1];
    const float* g     = (const float*)d_in[2];
    const float* W1    = (const float*)d_in[3];
    const float* b1    = (const float*)d_in[4];
    const float* W2    = (const float*)d_in[5];
    const float* b2    = (const float*)d_in[6];
    const float* ln1s  = (const float*)d_in[7];
    const float* ln1b  = (const float*)d_in[8];
    const float* ln2s  = (const float*)d_in[9];
    const float* ln2b  = (const float*)d_in[10];
    const float* lnfs  = (const float*)d_in[11];
    const float* lnfb  = (const float*)d_in[12];
    const float* headw = (const float*)d_in[13];
    const float* headb = (const float*)d_in[14];
    float* out = (float*)d_out;

    float *pX, *pS, *pD;
    bf16 *pYh, *pYl, *pYth, *pYtl, *pXGh, *pPh, *pPl, *pUh, *pUl;
    bf16 *pGh, *pW1h, *pW1l, *pW2h, *pW2l, *pHWh, *pHWl;
    cudaGetSymbolAddress((void**)&pX,   g_X);
    cudaGetSymbolAddress((void**)&pS,   g_S);
    cudaGetSymbolAddress((void**)&pD,   g_Dv);
    cudaGetSymbolAddress((void**)&pYh,  g_Yh);
    cudaGetSymbolAddress((void**)&pYl,  g_Yl);
    cudaGetSymbolAddress((void**)&pYth, g_Yth);
    cudaGetSymbolAddress((void**)&pYtl, g_Ytl);
    cudaGetSymbolAddress((void**)&pXGh, g_XGh);
    cudaGetSymbolAddress((void**)&pPh,  g_Ph);
    cudaGetSymbolAddress((void**)&pPl,  g_Pl);
    cudaGetSymbolAddress((void**)&pUh,  g_Uh);
    cudaGetSymbolAddress((void**)&pUl,  g_Ul);
    cudaGetSymbolAddress((void**)&pGh,  g_Gh);
    cudaGetSymbolAddress((void**)&pW1h, g_W1h);
    cudaGetSymbolAddress((void**)&pW1l, g_W1l);
    cudaGetSymbolAddress((void**)&pW2h, g_W2h);
    cudaGetSymbolAddress((void**)&pW2l, g_W2l);
    cudaGetSymbolAddress((void**)&pHWh, g_HWh);
    cudaGetSymbolAddress((void**)&pHWl, g_HWl);

    static bool attr_done = false;
    if (!attr_done) {
        cudaFuncSetAttribute(gemm_bf16<1, 0>, cudaFuncAttributeMaxDynamicSharedMemorySize, SMEM1);
        cudaFuncSetAttribute(gemm_bf16<1, 5>, cudaFuncAttributeMaxDynamicSharedMemorySize, SMEM1);
        cudaFuncSetAttribute(gemm_bf16<3, 1>, cudaFuncAttributeMaxDynamicSharedMemorySize, SMEM3);
        cudaFuncSetAttribute(gemm_bf16<3, 2>, cudaFuncAttributeMaxDynamicSharedMemorySize, SMEM3);
        cudaFuncSetAttribute(gemm_bf16<3, 3>, cudaFuncAttributeMaxDynamicSharedMemorySize, SMEM3);
        cudaFuncSetAttribute(gemm_bf16<3, 4>, cudaFuncAttributeMaxDynamicSharedMemorySize, SMEM3);
        attr_done = true;
    }

    // embedding + weight prep (per replay; small)
    embed_kernel<<<(NTOK * Dn) / 256, 256>>>(ids, emb, pX);
    split_hi<<<(Ln * Dn * Dn) / 256, 256>>>(g, pGh);
    transpose_split<<<dim3(Hn / 32, Dn / 32, Ln), dim3(32, 8)>>>(W1, pW1h, pW1l, Dn, Hn);
    transpose_split<<<dim3(Dn / 32, Hn / 32, Ln), dim3(32, 8)>>>(W2, pW2h, pW2l, Hn, Dn);
    transpose_split<<<dim3(Vn / 32, Dn / 32, 1),  dim3(32, 8)>>>(headw, pHWh, pHWl, Dn, Vn);

    for (int l = 0; l < Ln; l++) {
        layernorm_kernel<<<NTOK, 256>>>(pX, pYh, pYl, ln1s + l * Dn, ln1b + l * Dn);
        // Y^T per batch (needed by P@Y)
        transpose_pair<<<dim3(Tn / 32, Dn / 32, Bn), dim3(32, 8)>>>(pYh, pYl, pYth, pYtl);
        // XGh = bf16(Yh @ Gh)   (G symmetric; Gh rows [n][k])  1-term
        gemm_bf16<1, 5><<<dim3(NTOK / 128, Dn / 128, 1), 256, SMEM1>>>(
            pYh, nullptr, pGh + l * Dn * Dn, nullptr,
            nullptr, pXGh, nullptr, nullptr, Dn, Dn, 0, 0, 0);
        // S_b = XGh_b @ Yh_b^T  fp32 out, 1-term  (Yh is [T,D] = [N,K], K=D)
        gemm_bf16<1, 0><<<dim3(Tn / 128, Tn / 128, Bn), 256, SMEM1>>>(
            pXGh, nullptr, pYh, nullptr,
            pS, nullptr, nullptr, nullptr, Dn, Tn,
            (long long)Tn * Dn, (long long)Tn * Dn, (long long)Tn * Tn);
        diag_kernel<<<NTOK / 256, 256>>>(pS, pD);
        softmax_kernel<<<dim3(Tn, Bn), 256>>>(pS, pD, pPh, pPl);
        // x += P_b @ Y_b   3-term  (B = Y^T stored [N=D, K=T])
        gemm_bf16<3, 3><<<dim3(Tn / 128, Dn / 128, Bn), 256, SMEM3>>>(
            pPh, pPl, pYth, pYtl,
            pX, nullptr, nullptr, nullptr, Tn, Dn,
            (long long)Tn * Tn, (long long)Dn * Tn, (long long)Tn * Dn);
        layernorm_kernel<<<NTOK, 256>>>(pX, pYh, pYl, ln2s + l * Dn, ln2b + l * Dn);
        // U = split(gelu(H @ W1 + b1))   3-term  (W1t [H,D])
        gemm_bf16<3, 2><<<dim3(NTOK / 128, Hn / 128, 1), 256, SMEM3>>>(
            pYh, pYl, pW1h + l * Hn * Dn, pW1l + l * Hn * Dn,
            nullptr, pUh, pUl, b1 + l * Hn, Dn, Hn, 0, 0, 0);
        // x += U @ W2 + b2   3-term  (W2t [D,H])
        gemm_bf16<3, 4><<<dim3(NTOK / 128, Dn / 128, 1), 256, SMEM3>>>(
            pUh, pUl, pW2h + l * Dn * Hn, pW2l + l * Dn * Hn,
            pX, nullptr, nullptr, b2 + l * Dn, Hn, Dn, 0, 0, 0);
    }
    layernorm_kernel<<<NTOK, 256>>>(pX, pYh, pYl, lnfs, lnfb);
    // out = F @ head_w + head_b   3-term  (HWt [V,D])
    gemm_bf16<3, 1><<<dim3(NTOK / 128, Vn / 128, 1), 256, SMEM3>>>(
        pYh, pYl, pHWh, pHWl,
        out, nullptr, nullptr, headb, Dn, Vn, 0, 0, 0);
}